// round 6
// baseline (speedup 1.0000x reference)
#include <cuda_runtime.h>
#include <cuda_fp16.h>
#include <cstdint>

// ============================================================================
// Soft-quantization codebook kernel — legacy tensor path (sm_103 base target:
// tcgen05 is NOT available in this toolchain; use ldmatrix + mma.sync HMMA).
//
//   x:[262144] f32, anchors:[256] f32, embeddings:[256,64] f32, gamma -> out f32
//
// Persistent CTAs (2/SM). Per CTA-tile of 128 rows:
//   thread = row: windowed softmax weights (80 anchors) -> f16 -> smem A
//   warp  = 32 rows: m16n8k16 mma over K=256, N=64, f32 accum
//   epilogue scales by 1/sum(w) (shfl'd within the owning warp), STG float2.
// No per-tile __syncthreads: A rows + sums are warp-local by construction.
// ============================================================================

#define MTILE    128
#define KANCH    256
#define EDIM     64
#define WWIN     80                 // window anchors per row (10 octets of 8)
#define B_STRIDE 144                // bytes per B k-row: 64 f16 + 8 f16 pad
#define OFF_B    0
#define B_BYTES  (KANCH * B_STRIDE)             // 36864
#define OFF_A    B_BYTES                         // A: 32 planes x [128 x 16B]
#define A_BYTES  (32 * MTILE * 16)               // 65536
#define OFF_ANCH (OFF_A + A_BYTES)               // 102400
#define SMEM_TOTAL (OFF_ANCH + KANCH * 4)        // 103424

__device__ __forceinline__ uint32_t smem_u32(const void* p) {
    uint32_t a;
    asm("{ .reg .u64 t; cvta.to.shared.u64 t, %1; cvt.u32.u64 %0, t; }" : "=r"(a) : "l"(p));
    return a;
}

#define LDMATRIX_X4(r, addr)                                                      \
    asm volatile("ldmatrix.sync.aligned.m8n8.x4.shared.b16 {%0,%1,%2,%3}, [%4];"  \
        : "=r"((r)[0]), "=r"((r)[1]), "=r"((r)[2]), "=r"((r)[3]) : "r"(addr))

#define LDMATRIX_X2T(r0, r1, addr)                                                \
    asm volatile("ldmatrix.sync.aligned.m8n8.x2.trans.shared.b16 {%0,%1}, [%2];"  \
        : "=r"(r0), "=r"(r1) : "r"(addr))

#define MMA16816(c, a, b)                                                         \
    asm volatile("mma.sync.aligned.m16n8k16.row.col.f32.f16.f16.f32 "             \
        "{%0,%1,%2,%3}, {%4,%5,%6,%7}, {%8,%9}, {%0,%1,%2,%3};"                   \
        : "+f"((c)[0]), "+f"((c)[1]), "+f"((c)[2]), "+f"((c)[3])                  \
        : "r"((a)[0]), "r"((a)[1]), "r"((a)[2]), "r"((a)[3]),                     \
          "r"((b)[0]), "r"((b)[1]))

__global__ void __launch_bounds__(128, 2)
softquant_kernel(const float* __restrict__ xg,
                 const float* __restrict__ anchors_g,
                 const float* __restrict__ emb_g,
                 const float* __restrict__ gamma_g,
                 float* __restrict__ out_g,
                 int ntiles)
{
    extern __shared__ __align__(128) unsigned char smem[];
    const uint32_t smBase = smem_u32(smem);
    const uint32_t smB = smBase + OFF_B;
    const uint32_t smA = smBase + OFF_A;
    float* sAnch = reinterpret_cast<float*>(smem + OFF_ANCH);

    const int tid  = threadIdx.x;
    const int lane = tid & 31;
    const int warp = tid >> 5;
    const int R0   = warp * 32;

    // ---- one-time per CTA: E f32 -> f16 smem B [K=256 rows, 144B stride] ----
    #pragma unroll
    for (int i = 0; i < 32; i++) {
        const int idx4 = tid + i * 128;               // 4096 float4 total
        const float4 v = reinterpret_cast<const float4*>(emb_g)[idx4];
        const int base = idx4 * 4;
        const int k = base >> 6, n = base & 63;
        uint32_t h01, h23;
        asm("cvt.rn.f16x2.f32 %0, %1, %2;" : "=r"(h01) : "f"(v.y), "f"(v.x));
        asm("cvt.rn.f16x2.f32 %0, %1, %2;" : "=r"(h23) : "f"(v.w), "f"(v.z));
        asm volatile("st.shared.v2.b32 [%0], {%1, %2};"
                     :: "r"(smB + (uint32_t)(k * B_STRIDE + n * 2)), "r"(h01), "r"(h23));
    }
    sAnch[tid]       = anchors_g[tid];
    sAnch[tid + 128] = anchors_g[tid + 128];
    __syncthreads();

    const float g  = fabsf(gamma_g[0]);
    const float c1 = -g * 1.4426950408889634f;        // -gamma * log2(e)

    // per-lane ldmatrix address components
    const int mi = lane >> 3;                          // matrix index 0..3
    const uint32_t aLaneOff = (uint32_t)(R0 + ((mi & 1) << 3) + (lane & 7)) * 16u
                            + (uint32_t)(mi >> 1) * 2048u;   // +1 k-plane for a2/a3
    const uint32_t bLane = smB + (uint32_t)(lane & 15) * B_STRIDE;
    const uint32_t rowA  = smA + (uint32_t)tid * 16u;  // this thread's A row chunk base

    for (int tile = blockIdx.x; tile < ntiles; tile += gridDim.x) {
        // ================= weights: thread = row =================
        const float xv = xg[(size_t)tile * MTILE + tid];
        int i0 = __float2int_rn((xv + 6.0f) * (255.0f / 12.0f));
        i0 = min(max(i0, 0), 255);
        const int ks = min(max(i0 - 40, 0), KANCH - WWIN) & ~7;   // 8-aligned window start
        // zero this row across all 32 k-planes (16B per plane)
        #pragma unroll
        for (int p = 0; p < 32; p++)
            asm volatile("st.shared.v4.b32 [%0], {%1,%1,%1,%1};"
                         :: "r"(rowA + (uint32_t)p * 2048u), "r"(0u));
        float sum = 0.0f;
        const int pw = ks >> 3;
        #pragma unroll
        for (int oct = 0; oct < WWIN / 8; oct++) {
            uint32_t h[4];
            #pragma unroll
            for (int q = 0; q < 4; q++) {
                const int k = ks + oct * 8 + q * 2;
                const float2 a2 = *reinterpret_cast<const float2*>(sAnch + k);
                const float d0 = xv - a2.x, d1 = xv - a2.y;
                const float t0 = (c1 * d0) * d0, t1 = (c1 * d1) * d1;
                float e0, e1;
                asm("ex2.approx.ftz.f32 %0, %1;" : "=f"(e0) : "f"(t0));
                asm("ex2.approx.ftz.f32 %0, %1;" : "=f"(e1) : "f"(t1));
                sum += e0 + e1;
                asm("cvt.rn.f16x2.f32 %0, %1, %2;" : "=r"(h[q]) : "f"(e1), "f"(e0));
            }
            asm volatile("st.shared.v4.b32 [%0], {%1,%2,%3,%4};"
                         :: "r"(rowA + (uint32_t)(pw + oct) * 2048u),
                            "r"(h[0]), "r"(h[1]), "r"(h[2]), "r"(h[3]));
        }
        const float inv = 1.0f / sum;
        __syncwarp();   // A rows + sums are warp-local: warp-level sync suffices

        // ================= mma: warp tile M=32, N=64, K=256 =================
        float acc[2][8][4];
        #pragma unroll
        for (int mt = 0; mt < 2; mt++)
            #pragma unroll
            for (int nt = 0; nt < 8; nt++)
                #pragma unroll
                for (int j = 0; j < 4; j++) acc[mt][nt][j] = 0.0f;

        #pragma unroll
        for (int s = 0; s < 16; s++) {
            const uint32_t aAddr = smA + aLaneOff + (uint32_t)(2 * s) * 2048u;
            uint32_t a0[4], a1[4];
            LDMATRIX_X4(a0, aAddr);          // rows R0..R0+15
            LDMATRIX_X4(a1, aAddr + 256u);   // rows R0+16..R0+31
            const uint32_t bAddr = bLane + (uint32_t)(16 * s) * B_STRIDE;
            uint32_t b[8][2];
            #pragma unroll
            for (int nt = 0; nt < 8; nt++)
                LDMATRIX_X2T(b[nt][0], b[nt][1], bAddr + (uint32_t)(nt * 16));
            #pragma unroll
            for (int nt = 0; nt < 8; nt++) {
                MMA16816(acc[0][nt], a0, b[nt]);
                MMA16816(acc[1][nt], a1, b[nt]);
            }
        }
        __syncwarp();   // all lanes done reading sA before next tile overwrites it

        // ================= epilogue =================
        // inv for row-offset j*8 + lane/4 lives in lane (j*8 + lane/4)
        float invs[4];
        #pragma unroll
        for (int j = 0; j < 4; j++)
            invs[j] = __shfl_sync(0xffffffffu, inv, (lane >> 2) + j * 8);

        #pragma unroll
        for (int mt = 0; mt < 2; mt++) {
            const float iv0 = invs[mt * 2 + 0];
            const float iv1 = invs[mt * 2 + 1];
            const size_t row = (size_t)tile * MTILE + R0 + mt * 16 + (lane >> 2);
            #pragma unroll
            for (int nt = 0; nt < 8; nt++) {
                float* o = out_g + row * EDIM + nt * 8 + (lane & 3) * 2;
                float2 v0, v1;
                v0.x = acc[mt][nt][0] * iv0;  v0.y = acc[mt][nt][1] * iv0;
                v1.x = acc[mt][nt][2] * iv1;  v1.y = acc[mt][nt][3] * iv1;
                *reinterpret_cast<float2*>(o)            = v0;   // row
                *reinterpret_cast<float2*>(o + 8 * EDIM) = v1;   // row + 8
            }
        }
    }
}

extern "C" void kernel_launch(void* const* d_in, const int* in_sizes, int n_in,
                              void* d_out, int out_size) {
    const float* x       = (const float*)d_in[0];
    const float* anchors = (const float*)d_in[1];
    const float* emb     = (const float*)d_in[2];
    const float* gamma   = (const float*)d_in[3];
    float* out = (float*)d_out;

    const int rows   = in_sizes[0];          // 262144
    const int ntiles = rows / MTILE;         // 2048

    cudaFuncSetAttribute(softquant_kernel,
                         cudaFuncAttributeMaxDynamicSharedMemorySize, SMEM_TOTAL);
    int dev = 0, nsm = 148;
    cudaGetDevice(&dev);
    cudaDeviceGetAttribute(&nsm, cudaDevAttrMultiProcessorCount, dev);
    int grid = 2 * nsm;                      // persistent: 2 CTAs per SM
    if (grid > ntiles) grid = ntiles;

    softquant_kernel<<<grid, MTILE, SMEM_TOTAL>>>(x, anchors, emb, gamma, out, ntiles);
}

// round 7
// speedup vs baseline: 1.0636x; 1.0636x over previous
#include <cuda_runtime.h>
#include <cuda_fp16.h>
#include <cstdint>

// ============================================================================
// Soft-quantization codebook kernel — ldmatrix + mma.sync HMMA path (sm_103
// base target: tcgen05 unavailable in this toolchain).
//
// R6 -> R7 deltas (L1/shared was the 75%-busy pipe):
//   * warp-level k-range [sLo,sHi): MMA/ldmatrix only over union of windows
//   * zero-fill only warp-range planes outside each row's own window
//   * B loaded with ldmatrix.x4.trans (2 n-octets / instr)
// ============================================================================

#define MTILE    128
#define KANCH    256
#define EDIM     64
#define WWIN     80                 // window anchors per row (10 octets of 8)
#define B_STRIDE 144                // bytes per B k-row: 64 f16 + 8 f16 pad
#define OFF_B    0
#define B_BYTES  (KANCH * B_STRIDE)             // 36864
#define OFF_A    B_BYTES                         // A: 32 planes x [128 x 16B]
#define A_BYTES  (32 * MTILE * 16)               // 65536
#define OFF_ANCH (OFF_A + A_BYTES)               // 102400
#define SMEM_TOTAL (OFF_ANCH + KANCH * 4)        // 103424

__device__ __forceinline__ uint32_t smem_u32(const void* p) {
    uint32_t a;
    asm("{ .reg .u64 t; cvta.to.shared.u64 t, %1; cvt.u32.u64 %0, t; }" : "=r"(a) : "l"(p));
    return a;
}

#define LDMATRIX_X4(r, addr)                                                      \
    asm volatile("ldmatrix.sync.aligned.m8n8.x4.shared.b16 {%0,%1,%2,%3}, [%4];"  \
        : "=r"((r)[0]), "=r"((r)[1]), "=r"((r)[2]), "=r"((r)[3]) : "r"(addr))

#define LDMATRIX_X4T(r0, r1, r2, r3, addr)                                        \
    asm volatile("ldmatrix.sync.aligned.m8n8.x4.trans.shared.b16 {%0,%1,%2,%3}, [%4];" \
        : "=r"(r0), "=r"(r1), "=r"(r2), "=r"(r3) : "r"(addr))

#define MMA16816(c, a, b)                                                         \
    asm volatile("mma.sync.aligned.m16n8k16.row.col.f32.f16.f16.f32 "             \
        "{%0,%1,%2,%3}, {%4,%5,%6,%7}, {%8,%9}, {%0,%1,%2,%3};"                   \
        : "+f"((c)[0]), "+f"((c)[1]), "+f"((c)[2]), "+f"((c)[3])                  \
        : "r"((a)[0]), "r"((a)[1]), "r"((a)[2]), "r"((a)[3]),                     \
          "r"((b)[0]), "r"((b)[1]))

__global__ void __launch_bounds__(128, 2)
softquant_kernel(const float* __restrict__ xg,
                 const float* __restrict__ anchors_g,
                 const float* __restrict__ emb_g,
                 const float* __restrict__ gamma_g,
                 float* __restrict__ out_g,
                 int ntiles)
{
    extern __shared__ __align__(128) unsigned char smem[];
    const uint32_t smBase = smem_u32(smem);
    const uint32_t smB = smBase + OFF_B;
    const uint32_t smA = smBase + OFF_A;
    float* sAnch = reinterpret_cast<float*>(smem + OFF_ANCH);

    const int tid  = threadIdx.x;
    const int lane = tid & 31;
    const int warp = tid >> 5;
    const int R0   = warp * 32;

    // ---- one-time per CTA: E f32 -> f16 smem B [K=256 rows, 144B stride] ----
    #pragma unroll
    for (int i = 0; i < 32; i++) {
        const int idx4 = tid + i * 128;               // 4096 float4 total
        const float4 v = reinterpret_cast<const float4*>(emb_g)[idx4];
        const int base = idx4 * 4;
        const int k = base >> 6, n = base & 63;
        uint32_t h01, h23;
        asm("cvt.rn.f16x2.f32 %0, %1, %2;" : "=r"(h01) : "f"(v.y), "f"(v.x));
        asm("cvt.rn.f16x2.f32 %0, %1, %2;" : "=r"(h23) : "f"(v.w), "f"(v.z));
        asm volatile("st.shared.v2.b32 [%0], {%1, %2};"
                     :: "r"(smB + (uint32_t)(k * B_STRIDE + n * 2)), "r"(h01), "r"(h23));
    }
    sAnch[tid]       = anchors_g[tid];
    sAnch[tid + 128] = anchors_g[tid + 128];
    __syncthreads();

    const float g  = fabsf(gamma_g[0]);
    const float c1 = -g * 1.4426950408889634f;        // -gamma * log2(e)

    // per-lane ldmatrix address components
    const int mi = lane >> 3;                          // matrix index 0..3
    const uint32_t aLaneOff = (uint32_t)(R0 + ((mi & 1) << 3) + (lane & 7)) * 16u
                            + (uint32_t)(mi >> 1) * 2048u;   // +1 k-plane for a2/a3
    // B x4.trans: lanes 0-15 -> k-rows 0..15, n-octet 0; lanes 16-31 -> same k, n-octet +1
    const uint32_t bLane = smB + (uint32_t)(lane & 15) * B_STRIDE + (uint32_t)(lane >> 4) * 16u;
    const uint32_t rowA  = smA + (uint32_t)tid * 16u;  // this thread's A row chunk base

    for (int tile = blockIdx.x; tile < ntiles; tile += gridDim.x) {
        // ================= weights: thread = row =================
        const float xv = xg[(size_t)tile * MTILE + tid];
        int i0 = __float2int_rn((xv + 6.0f) * (255.0f / 12.0f));
        i0 = min(max(i0, 0), 255);
        const int ks = min(max(i0 - 40, 0), KANCH - WWIN) & ~7;   // 8-aligned window start
        const int pw = ks >> 3;                                   // first own octet-plane

        // warp k-range: union of [ks, ks+WWIN) over all 32 lanes
        int kmin = ks, kmax = ks + WWIN;
        #pragma unroll
        for (int off = 16; off > 0; off >>= 1) {
            kmin = min(kmin, __shfl_xor_sync(0xffffffffu, kmin, off));
            kmax = max(kmax, __shfl_xor_sync(0xffffffffu, kmax, off));
        }
        const int sLo = kmin >> 4;                 // first K-step (16 k each)
        const int sHi = (kmax + 15) >> 4;          // exclusive
        const int pLo = 2 * sLo, pHi = 2 * sHi;    // plane range read by MMA

        // zero only planes in warp range but outside this row's own window
        for (int p = pLo; p < pHi; p++) {
            if (p < pw || p >= pw + (WWIN / 8))
                asm volatile("st.shared.v4.b32 [%0], {%1,%1,%1,%1};"
                             :: "r"(rowA + (uint32_t)p * 2048u), "r"(0u));
        }

        float sum = 0.0f;
        #pragma unroll
        for (int oct = 0; oct < WWIN / 8; oct++) {
            uint32_t h[4];
            #pragma unroll
            for (int q = 0; q < 4; q++) {
                const int k = ks + oct * 8 + q * 2;
                const float2 a2 = *reinterpret_cast<const float2*>(sAnch + k);
                const float d0 = xv - a2.x, d1 = xv - a2.y;
                const float t0 = (c1 * d0) * d0, t1 = (c1 * d1) * d1;
                float e0, e1;
                asm("ex2.approx.ftz.f32 %0, %1;" : "=f"(e0) : "f"(t0));
                asm("ex2.approx.ftz.f32 %0, %1;" : "=f"(e1) : "f"(t1));
                sum += e0 + e1;
                asm("cvt.rn.f16x2.f32 %0, %1, %2;" : "=r"(h[q]) : "f"(e1), "f"(e0));
            }
            asm volatile("st.shared.v4.b32 [%0], {%1,%2,%3,%4};"
                         :: "r"(rowA + (uint32_t)(pw + oct) * 2048u),
                            "r"(h[0]), "r"(h[1]), "r"(h[2]), "r"(h[3]));
        }
        const float inv = 1.0f / sum;
        __syncwarp();   // A rows + sums are warp-local: warp-level sync suffices

        // ================= mma: warp tile M=32, N=64, K = 16*(sHi-sLo) =================
        float acc[2][8][4];
        #pragma unroll
        for (int mt = 0; mt < 2; mt++)
            #pragma unroll
            for (int nt = 0; nt < 8; nt++)
                #pragma unroll
                for (int j = 0; j < 4; j++) acc[mt][nt][j] = 0.0f;

        for (int s = sLo; s < sHi; s++) {
            const uint32_t aAddr = smA + aLaneOff + (uint32_t)(2 * s) * 2048u;
            uint32_t a0[4], a1[4];
            LDMATRIX_X4(a0, aAddr);          // rows R0..R0+15
            LDMATRIX_X4(a1, aAddr + 256u);   // rows R0+16..R0+31
            const uint32_t bAddr = bLane + (uint32_t)(16 * s) * B_STRIDE;
            uint32_t b[8][2];
            #pragma unroll
            for (int nt = 0; nt < 8; nt += 2)   // x4.trans: two n-octets per instr
                LDMATRIX_X4T(b[nt][0], b[nt][1], b[nt + 1][0], b[nt + 1][1],
                             bAddr + (uint32_t)(nt * 16));
            #pragma unroll
            for (int nt = 0; nt < 8; nt++) {
                MMA16816(acc[0][nt], a0, b[nt]);
                MMA16816(acc[1][nt], a1, b[nt]);
            }
        }
        __syncwarp();   // all lanes done reading sA before next tile overwrites it

        // ================= epilogue =================
        float invs[4];
        #pragma unroll
        for (int j = 0; j < 4; j++)
            invs[j] = __shfl_sync(0xffffffffu, inv, (lane >> 2) + j * 8);

        #pragma unroll
        for (int mt = 0; mt < 2; mt++) {
            const float iv0 = invs[mt * 2 + 0];
            const float iv1 = invs[mt * 2 + 1];
            const size_t row = (size_t)tile * MTILE + R0 + mt * 16 + (lane >> 2);
            #pragma unroll
            for (int nt = 0; nt < 8; nt++) {
                float* o = out_g + row * EDIM + nt * 8 + (lane & 3) * 2;
                float2 v0, v1;
                v0.x = acc[mt][nt][0] * iv0;  v0.y = acc[mt][nt][1] * iv0;
                v1.x = acc[mt][nt][2] * iv1;  v1.y = acc[mt][nt][3] * iv1;
                *reinterpret_cast<float2*>(o)            = v0;   // row
                *reinterpret_cast<float2*>(o + 8 * EDIM) = v1;   // row + 8
            }
        }
    }
}

extern "C" void kernel_launch(void* const* d_in, const int* in_sizes, int n_in,
                              void* d_out, int out_size) {
    const float* x       = (const float*)d_in[0];
    const float* anchors = (const float*)d_in[1];
    const float* emb     = (const float*)d_in[2];
    const float* gamma   = (const float*)d_in[3];
    float* out = (float*)d_out;

    const int rows   = in_sizes[0];          // 262144
    const int ntiles = rows / MTILE;         // 2048

    cudaFuncSetAttribute(softquant_kernel,
                         cudaFuncAttributeMaxDynamicSharedMemorySize, SMEM_TOTAL);
    int dev = 0, nsm = 148;
    cudaGetDevice(&dev);
    cudaDeviceGetAttribute(&nsm, cudaDevAttrMultiProcessorCount, dev);
    int grid = 2 * nsm;                      // persistent: 2 CTAs per SM
    if (grid > ntiles) grid = ntiles;

    softquant_kernel<<<grid, MTILE, SMEM_TOTAL>>>(x, anchors, emb, gamma, out, ntiles);
}